// round 1
// baseline (speedup 1.0000x reference)
#include <cuda_runtime.h>
#include <stdint.h>

// Complex linear: out_re = x_re@Re^T - x_im@Im^T ; out_im = x_re@Im^T + x_im@Re^T
// Folded into one real GEMM: X = [x_re | x_im] (N x 1024), W = [[Re, -Im],[Im, Re]] (1024 x 1024)
// out[n, 0:512] -> out_re, out[n, 512:1024] -> out_im, scattered to (2, N, 512) layout.

#define M_ROWS 100000
#define KDIM   1024
#define NDIM   1024

#define BM 128
#define BN 128
#define BK 32
#define STRIDE 36               // BK + 4 pad: bank(addr) == lane permutation -> conflict-free
#define STAGE_FLOATS (BM * STRIDE)  // 4608 floats per tile
#define SMEM_FLOATS_PER_STAGE (2 * STAGE_FLOATS)  // A + B

// Pre-built combined weight matrix, already rounded to tf32. 4 MB static device array.
__device__ float g_W[NDIM * KDIM];

__device__ __forceinline__ uint32_t f2tf32(float f) {
    uint32_t r;
    asm("cvt.rna.tf32.f32 %0, %1;" : "=r"(r) : "f"(f));
    return r;
}

__global__ void build_W_kernel(const float* __restrict__ Re, const float* __restrict__ Im) {
    int idx = blockIdx.x * blockDim.x + threadIdx.x;   // 1M threads exactly
    int o = idx >> 10;
    int k = idx & 1023;
    float v;
    if (o < 512) v = (k < 512) ? Re[o * 512 + k] : -Im[o * 512 + (k - 512)];
    else         v = (k < 512) ? Im[(o - 512) * 512 + k] : Re[(o - 512) * 512 + (k - 512)];
    g_W[idx] = __uint_as_float(f2tf32(v));
}

__device__ __forceinline__ void cp_async16(uint32_t saddr, const void* gptr, bool pred) {
    int sz = pred ? 16 : 0;
    asm volatile("cp.async.cg.shared.global [%0], [%1], 16, %2;\n"
                 :: "r"(saddr), "l"(gptr), "r"(sz));
}
__device__ __forceinline__ void cp_async_commit() {
    asm volatile("cp.async.commit_group;\n" ::: "memory");
}
template <int N>
__device__ __forceinline__ void cp_async_wait() {
    asm volatile("cp.async.wait_group %0;\n" :: "n"(N) : "memory");
}

__device__ __forceinline__ void mma_tf32(float* c, const uint32_t* a, uint32_t b0, uint32_t b1) {
    asm volatile(
        "mma.sync.aligned.m16n8k8.row.col.f32.tf32.tf32.f32 "
        "{%0,%1,%2,%3}, {%4,%5,%6,%7}, {%8,%9}, {%0,%1,%2,%3};\n"
        : "+f"(c[0]), "+f"(c[1]), "+f"(c[2]), "+f"(c[3])
        : "r"(a[0]), "r"(a[1]), "r"(a[2]), "r"(a[3]), "r"(b0), "r"(b1));
}

__global__ void __launch_bounds__(256, 2)
cplx_gemm_kernel(const float* __restrict__ xre, const float* __restrict__ xim,
                 float* __restrict__ out)
{
    extern __shared__ float smem[];  // [2 stages][A 4608 | B 4608]

    const int n_tile = blockIdx.x;   // 0..7  (fastest -> consecutive blocks share A rows in L2)
    const int m_tile = blockIdx.y;   // 0..781
    const int tid  = threadIdx.x;
    const int lane = tid & 31;
    const int warp = tid >> 5;
    const int wm0 = (warp & 3) * 32;   // warp tile: 32 (M) x 64 (N)
    const int wn0 = (warp >> 2) * 64;
    const int g = lane >> 2;           // groupID
    const int t = lane & 3;            // threadID_in_group

    float acc[2][8][4];
#pragma unroll
    for (int mi = 0; mi < 2; mi++)
#pragma unroll
        for (int ni = 0; ni < 8; ni++)
#pragma unroll
            for (int r = 0; r < 4; r++) acc[mi][ni][r] = 0.0f;

    const int NT = KDIM / BK;  // 32 k-iterations

    // ---- loader: stage kt into buffer buf ----
    auto issue = [&](int kt, int buf) {
        const int k0 = kt * BK;
        const float* abase = (k0 < 512) ? (xre + k0) : (xim + (k0 - 512));
        float* As = smem + buf * SMEM_FLOATS_PER_STAGE;
        float* Bs = As + STAGE_FLOATS;
        const float* wbase = g_W + (size_t)(n_tile * BN) * KDIM + k0;
#pragma unroll
        for (int i = 0; i < 4; i++) {
            int idx = tid + i * 256;       // 0..1023
            int row = idx >> 3;            // 0..127
            int ch  = (idx & 7) * 4;       // 0,4,...,28
            // A tile (guarded rows on last M-tile)
            int grow = m_tile * BM + row;
            bool ok = grow < M_ROWS;
            int grow_c = ok ? grow : (M_ROWS - 1);
            uint32_t sa = (uint32_t)__cvta_generic_to_shared(As + row * STRIDE + ch);
            cp_async16(sa, abase + (size_t)grow_c * 512 + ch, ok);
            // B tile (always in-bounds)
            uint32_t sb = (uint32_t)__cvta_generic_to_shared(Bs + row * STRIDE + ch);
            cp_async16(sb, wbase + (size_t)row * KDIM + ch, true);
        }
        cp_async_commit();
    };

    // ---- compute on buffer buf ----
    auto compute = [&](int buf) {
        const float* As = smem + buf * SMEM_FLOATS_PER_STAGE;
        const float* Bs = As + STAGE_FLOATS;
#pragma unroll
        for (int ks = 0; ks < 4; ks++) {
            const int kk = ks * 8 + t;
            uint32_t a[2][4];
#pragma unroll
            for (int mi = 0; mi < 2; mi++) {
                const float* p = As + (wm0 + mi * 16 + g) * STRIDE + kk;
                a[mi][0] = f2tf32(p[0]);
                a[mi][1] = f2tf32(p[8 * STRIDE]);
                a[mi][2] = f2tf32(p[4]);
                a[mi][3] = f2tf32(p[8 * STRIDE + 4]);
            }
#pragma unroll
            for (int ni = 0; ni < 8; ni++) {
                const float* p = Bs + (wn0 + ni * 8 + g) * STRIDE + kk;
                uint32_t b0 = __float_as_uint(p[0]);
                uint32_t b1 = __float_as_uint(p[4]);
#pragma unroll
                for (int mi = 0; mi < 2; mi++)
                    mma_tf32(acc[mi][ni], a[mi], b0, b1);
            }
        }
    };

    // ---- software-pipelined mainloop (2-stage) ----
    issue(0, 0);
    for (int kt = 0; kt < NT; kt++) {
        if (kt + 1 < NT) {
            issue(kt + 1, (kt + 1) & 1);
            cp_async_wait<1>();
        } else {
            cp_async_wait<0>();
        }
        __syncthreads();
        compute(kt & 1);
        __syncthreads();
    }

    // ---- epilogue: scatter into (2, N, 512) ----
#pragma unroll
    for (int mi = 0; mi < 2; mi++) {
        int row = m_tile * BM + wm0 + mi * 16 + g;
        // M_ROWS % 16 == 0, so row < M_ROWS implies row+8 < M_ROWS too
        if (row < M_ROWS) {
#pragma unroll
            for (int ni = 0; ni < 8; ni++) {
                int co = n_tile * BN + wn0 + ni * 8 + (t << 1);
                int half = co >> 9;
                int col = co & 511;
                float* op = out + (size_t)half * ((size_t)M_ROWS * 512)
                                + (size_t)row * 512 + col;
                *reinterpret_cast<float2*>(op) = make_float2(acc[mi][ni][0], acc[mi][ni][1]);
                *reinterpret_cast<float2*>(op + 8 * 512) = make_float2(acc[mi][ni][2], acc[mi][ni][3]);
            }
        }
    }
}

extern "C" void kernel_launch(void* const* d_in, const int* in_sizes, int n_in,
                              void* d_out, int out_size)
{
    const float* xre = (const float*)d_in[0];
    const float* xim = (const float*)d_in[1];
    const float* Re  = (const float*)d_in[2];
    const float* Im  = (const float*)d_in[3];
    float* out = (float*)d_out;

    // Idempotent, not a stream op — safe under graph capture.
    cudaFuncSetAttribute(cplx_gemm_kernel,
                         cudaFuncAttributeMaxDynamicSharedMemorySize,
                         2 * SMEM_FLOATS_PER_STAGE * (int)sizeof(float));

    build_W_kernel<<<(NDIM * KDIM) / 256, 256>>>(Re, Im);

    dim3 grid(NDIM / BN, (M_ROWS + BM - 1) / BM);  // (8, 782)
    cplx_gemm_kernel<<<grid, 256, 2 * SMEM_FLOATS_PER_STAGE * sizeof(float)>>>(xre, xim, out);
}